// round 2
// baseline (speedup 1.0000x reference)
#include <cuda_runtime.h>

#define NN 200000
#define DD 64
#define EE 600000
#define TE 1200000   // 2*EE directed edges after symmetrization

// Scratch: __device__ globals (no allocation allowed anywhere).
__device__ float g_xn[(size_t)NN * DD];   // l2-normalized x
__device__ float g_x1[(size_t)NN * DD];   // layer-1 output
__device__ float g_agg[(size_t)NN * DD];  // scatter accumulator
__device__ float g_inv[NN];               // 1 / max(in_degree, 1)

// ---------------------------------------------------------------------------
// Degree count: one thread per directed edge, atomicAdd 1.0 at dst.
// Edge e: src = ei[e] always; dst = ei[e+EE] for e<EE, ei[e-EE] for e>=EE.
__global__ void k_count(const int* __restrict__ ei) {
    int e = blockIdx.x * blockDim.x + threadIdx.x;
    if (e >= TE) return;
    int dst = (e < EE) ? ei[e + EE] : ei[e - EE];
    if ((unsigned)dst < (unsigned)NN) atomicAdd(&g_inv[dst], 1.0f);
}

__global__ void k_finalize_inv() {
    int i = blockIdx.x * blockDim.x + threadIdx.x;
    if (i >= NN) return;
    g_inv[i] = 1.0f / fmaxf(g_inv[i], 1.0f);
}

// ---------------------------------------------------------------------------
// Row-wise L2 normalize: one warp per row, float2 per lane (64 floats/row).
__global__ void k_norm(const float* __restrict__ x) {
    int row  = blockIdx.x * 8 + (threadIdx.x >> 5);
    int lane = threadIdx.x & 31;
    if (row >= NN) return;
    const float2 v = *(const float2*)(x + (size_t)row * DD + lane * 2);
    float s = v.x * v.x + v.y * v.y;
    #pragma unroll
    for (int o = 16; o; o >>= 1) s += __shfl_xor_sync(0xffffffffu, s, o);
    float inv = 1.0f / fmaxf(sqrtf(s), 1e-12f);
    float2 r = make_float2(v.x * inv, v.y * inv);
    *(float2*)(g_xn + (size_t)row * DD + lane * 2) = r;
}

// ---------------------------------------------------------------------------
// Scatter conv: 16 threads per edge, each owns a float4 (16 lanes * 4 = 64).
// Vector atomicAdd(float4*) (sm_90+) -> REDG.128, 4x fewer L2 atomic ops.
__global__ void k_scatter(const float* __restrict__ xin,
                          const int* __restrict__ ei,
                          const float* __restrict__ w) {
    int tid = blockIdx.x * blockDim.x + threadIdx.x;
    int e = tid >> 4;
    if (e >= TE) return;
    int lane = tid & 15;
    int src = ei[e];
    int dst = (e < EE) ? ei[e + EE] : ei[e - EE];
    if ((unsigned)src >= (unsigned)NN || (unsigned)dst >= (unsigned)NN) return;
    float ww = w[e];
    float4 v = *(const float4*)(xin + (size_t)src * DD + lane * 4);
    v.x *= ww; v.y *= ww; v.z *= ww; v.w *= ww;
    atomicAdd((float4*)(g_agg + (size_t)dst * DD + lane * 4), v);
}

// ---------------------------------------------------------------------------
// Epilogue 1: x1 = leaky_relu(agg * inv_denom[row]); float4 per thread.
__global__ void k_post1() {
    int i = blockIdx.x * blockDim.x + threadIdx.x;   // over NN*DD/4
    if (i >= NN * (DD / 4)) return;
    int row = i >> 4;                                 // (i*4)/64
    float s = g_inv[row];
    float4 a = ((const float4*)g_agg)[i];
    a.x *= s; a.y *= s; a.z *= s; a.w *= s;
    a.x = a.x >= 0.f ? a.x : 0.01f * a.x;
    a.y = a.y >= 0.f ? a.y : 0.01f * a.y;
    a.z = a.z >= 0.f ? a.z : 0.01f * a.z;
    a.w = a.w >= 0.f ? a.w : 0.01f * a.w;
    ((float4*)g_x1)[i] = a;
}

// Epilogue 2: out = xn + x1 + leaky_relu(agg * inv_denom[row]).
__global__ void k_final(float* __restrict__ out) {
    int i = blockIdx.x * blockDim.x + threadIdx.x;   // over NN*DD/4
    if (i >= NN * (DD / 4)) return;
    int row = i >> 4;
    float s = g_inv[row];
    float4 a = ((const float4*)g_agg)[i];
    a.x *= s; a.y *= s; a.z *= s; a.w *= s;
    a.x = a.x >= 0.f ? a.x : 0.01f * a.x;
    a.y = a.y >= 0.f ? a.y : 0.01f * a.y;
    a.z = a.z >= 0.f ? a.z : 0.01f * a.z;
    a.w = a.w >= 0.f ? a.w : 0.01f * a.w;
    float4 xn = ((const float4*)g_xn)[i];
    float4 x1 = ((const float4*)g_x1)[i];
    a.x += xn.x + x1.x;
    a.y += xn.y + x1.y;
    a.z += xn.z + x1.z;
    a.w += xn.w + x1.w;
    ((float4*)out)[i] = a;
}

// ---------------------------------------------------------------------------
extern "C" void kernel_launch(void* const* d_in, const int* in_sizes, int n_in,
                              void* d_out, int out_size) {
    const float* emb = (const float*)d_in[0];   // [NN, DD] float32
    const int*   ei  = (const int*)d_in[1];     // [2, EE] int32 (jax default x64 off)
    const float* w   = (const float*)d_in[2];   // [TE, 1] float32
    float* out = (float*)d_out;

    void *p_inv, *p_agg, *p_xn, *p_x1;
    cudaGetSymbolAddress(&p_inv, g_inv);
    cudaGetSymbolAddress(&p_agg, g_agg);
    cudaGetSymbolAddress(&p_xn,  g_xn);
    cudaGetSymbolAddress(&p_x1,  g_x1);

    const int THR = 256;
    const int elem4 = NN * (DD / 4);

    // degrees -> inverse denominators
    cudaMemsetAsync(p_inv, 0, NN * sizeof(float));
    k_count<<<(TE + THR - 1) / THR, THR>>>(ei);
    k_finalize_inv<<<(NN + THR - 1) / THR, THR>>>();

    // x = l2norm(emb)
    k_norm<<<(NN + 7) / 8, THR>>>(emb);

    // layer 1: agg = scatter(xn); x1 = leaky(agg * inv)
    cudaMemsetAsync(p_agg, 0, (size_t)NN * DD * sizeof(float));
    k_scatter<<<(TE * 16 + THR - 1) / THR, THR>>>((const float*)p_xn, ei, w);
    k_post1<<<(elem4 + THR - 1) / THR, THR>>>();

    // layer 2: agg = scatter(x1); out = xn + x1 + leaky(agg * inv)
    cudaMemsetAsync(p_agg, 0, (size_t)NN * DD * sizeof(float));
    k_scatter<<<(TE * 16 + THR - 1) / THR, THR>>>((const float*)p_x1, ei, w);
    k_final<<<(elem4 + THR - 1) / THR, THR>>>(out);
}

// round 3
// speedup vs baseline: 1.3803x; 1.3803x over previous
#include <cuda_runtime.h>

#define NN 200000
#define DD 64
#define EE 600000
#define TE 1200000           // 2*EE directed edges after symmetrization
#define NB 196               // ceil(NN / 1024) scan blocks

// Scratch: __device__ globals (no allocation allowed anywhere).
__device__ float g_xn[(size_t)NN * DD];    // l2-normalized x
__device__ float g_x1[(size_t)NN * DD];    // layer-1 output
__device__ int   g_cnt[NN];                // in-degree
__device__ float g_inv[NN];                // 1 / max(in_degree, 1)
__device__ int   g_off[NN + 1];            // CSR row offsets (exclusive scan)
__device__ int   g_cur[NN];                // fill cursors
__device__ int   g_bsum[256];              // scan block sums
__device__ int   g_csr_src[TE];            // CSR: source node per slot
__device__ float g_csr_w[TE];              // CSR: edge weight per slot

// ---------------------------------------------------------------------------
// Degree histogram: one thread per directed edge.
// Edge e: src = ei[e]; dst = ei[e+EE] for e<EE, ei[e-EE] for e>=EE.
__global__ void k_count(const int* __restrict__ ei) {
    int e = blockIdx.x * blockDim.x + threadIdx.x;
    if (e >= TE) return;
    int dst = (e < EE) ? ei[e + EE] : ei[e - EE];
    if ((unsigned)dst < (unsigned)NN) atomicAdd(&g_cnt[dst], 1);
}

__global__ void k_inv() {
    int i = blockIdx.x * blockDim.x + threadIdx.x;
    if (i >= NN) return;
    g_inv[i] = 1.0f / fmaxf((float)g_cnt[i], 1.0f);
}

// ---------------------------------------------------------------------------
// Exclusive scan over g_cnt (3 kernels). Each scan1 block handles 1024 elems.
__global__ void k_scan1() {
    __shared__ int sh[256];
    int t = threadIdx.x;
    int base = blockIdx.x * 1024 + t * 4;
    int v0 = (base + 0 < NN) ? g_cnt[base + 0] : 0;
    int v1 = (base + 1 < NN) ? g_cnt[base + 1] : 0;
    int v2 = (base + 2 < NN) ? g_cnt[base + 2] : 0;
    int v3 = (base + 3 < NN) ? g_cnt[base + 3] : 0;
    int s = v0 + v1 + v2 + v3;
    sh[t] = s;
    __syncthreads();
    #pragma unroll
    for (int o = 1; o < 256; o <<= 1) {
        int x = (t >= o) ? sh[t - o] : 0;
        __syncthreads();
        sh[t] += x;
        __syncthreads();
    }
    int excl = sh[t] - s;
    if (base + 0 < NN) g_off[base + 0] = excl;
    if (base + 1 < NN) g_off[base + 1] = excl + v0;
    if (base + 2 < NN) g_off[base + 2] = excl + v0 + v1;
    if (base + 3 < NN) g_off[base + 3] = excl + v0 + v1 + v2;
    if (t == 255) g_bsum[blockIdx.x] = sh[255];
}

__global__ void k_scan2() {   // single block scans the 196 block sums
    __shared__ int sh[256];
    int t = threadIdx.x;
    int v = (t < NB) ? g_bsum[t] : 0;
    sh[t] = v;
    __syncthreads();
    #pragma unroll
    for (int o = 1; o < 256; o <<= 1) {
        int x = (t >= o) ? sh[t - o] : 0;
        __syncthreads();
        sh[t] += x;
        __syncthreads();
    }
    if (t < NB) g_bsum[t] = sh[t] - v;   // exclusive
}

__global__ void k_scan3() {
    int i = blockIdx.x * blockDim.x + threadIdx.x;
    if (i < NN) {
        int o = g_off[i] + g_bsum[i >> 10];
        g_off[i] = o;
        g_cur[i] = o;
    }
    if (i == 0) g_off[NN] = TE;
}

// ---------------------------------------------------------------------------
// CSR fill: place (src, w) into dst's bucket.
__global__ void k_fill(const int* __restrict__ ei, const float* __restrict__ w) {
    int e = blockIdx.x * blockDim.x + threadIdx.x;
    if (e >= TE) return;
    int src = ei[e];
    int dst = (e < EE) ? ei[e + EE] : ei[e - EE];
    if ((unsigned)src >= (unsigned)NN || (unsigned)dst >= (unsigned)NN) return;
    int pos = atomicAdd(&g_cur[dst], 1);
    g_csr_src[pos] = src;
    g_csr_w[pos] = w[e];
}

// ---------------------------------------------------------------------------
// Row-wise L2 normalize: one warp per row, float2 per lane (64 floats/row).
__global__ void k_norm(const float* __restrict__ x) {
    int row  = blockIdx.x * 8 + (threadIdx.x >> 5);
    int lane = threadIdx.x & 31;
    if (row >= NN) return;
    const float2 v = *(const float2*)(x + (size_t)row * DD + lane * 2);
    float s = v.x * v.x + v.y * v.y;
    #pragma unroll
    for (int o = 16; o; o >>= 1) s += __shfl_xor_sync(0xffffffffu, s, o);
    float inv = 1.0f / fmaxf(sqrtf(s), 1e-12f);
    *(float2*)(g_xn + (size_t)row * DD + lane * 2) = make_float2(v.x * inv, v.y * inv);
}

// ---------------------------------------------------------------------------
// Pull-based conv: one warp per dst row, float2 per lane; atomic-free.
// Fused epilogue: leaky(acc * inv); FINAL also adds xn + x1 and writes d_out.
template <bool FINAL>
__global__ void k_gather(const float* __restrict__ xin, float* __restrict__ xout) {
    int row  = blockIdx.x * 8 + (threadIdx.x >> 5);
    int lane = threadIdx.x & 31;
    if (row >= NN) return;
    int start = g_off[row];
    int end   = g_off[row + 1];
    float2 acc = make_float2(0.f, 0.f);
    for (int b = start; b < end; b += 32) {
        int idx = b + lane;
        int   s  = 0;
        float ww = 0.f;
        if (idx < end) { s = g_csr_src[idx]; ww = g_csr_w[idx]; }
        int m = min(32, end - b);
        for (int j = 0; j < m; j++) {
            int   sj = __shfl_sync(0xffffffffu, s, j);
            float wj = __shfl_sync(0xffffffffu, ww, j);
            const float2 v = *(const float2*)(xin + (size_t)sj * DD + lane * 2);
            acc.x += wj * v.x;
            acc.y += wj * v.y;
        }
    }
    float sc = g_inv[row];
    acc.x *= sc; acc.y *= sc;
    acc.x = acc.x >= 0.f ? acc.x : 0.01f * acc.x;
    acc.y = acc.y >= 0.f ? acc.y : 0.01f * acc.y;
    size_t o = (size_t)row * DD + lane * 2;
    if (FINAL) {
        float2 xn = *(const float2*)(g_xn + o);
        float2 x1 = *(const float2*)(g_x1 + o);
        acc.x += xn.x + x1.x;
        acc.y += xn.y + x1.y;
    }
    *(float2*)(xout + o) = acc;
}

// ---------------------------------------------------------------------------
extern "C" void kernel_launch(void* const* d_in, const int* in_sizes, int n_in,
                              void* d_out, int out_size) {
    const float* emb = (const float*)d_in[0];   // [NN, DD] float32
    const int*   ei  = (const int*)d_in[1];     // [2, EE] int32
    const float* w   = (const float*)d_in[2];   // [TE, 1] float32
    float* out = (float*)d_out;

    void *p_cnt, *p_xn, *p_x1;
    cudaGetSymbolAddress(&p_cnt, g_cnt);
    cudaGetSymbolAddress(&p_xn,  g_xn);
    cudaGetSymbolAddress(&p_x1,  g_x1);

    const int THR = 256;

    // CSR build: degrees -> scan -> fill
    cudaMemsetAsync(p_cnt, 0, NN * sizeof(int));
    k_count<<<(TE + THR - 1) / THR, THR>>>(ei);
    k_inv<<<(NN + THR - 1) / THR, THR>>>();
    k_scan1<<<NB, THR>>>();
    k_scan2<<<1, THR>>>();
    k_scan3<<<(NN + THR - 1) / THR, THR>>>();
    k_fill<<<(TE + THR - 1) / THR, THR>>>(ei, w);

    // x = l2norm(emb)
    k_norm<<<(NN + 7) / 8, THR>>>(emb);

    // layer 1: x1 = leaky(gather(xn) * inv)          (fused epilogue)
    k_gather<false><<<(NN + 7) / 8, THR>>>((const float*)p_xn, (float*)p_x1);
    // layer 2: out = xn + x1 + leaky(gather(x1)*inv) (fused epilogue)
    k_gather<true><<<(NN + 7) / 8, THR>>>((const float*)p_x1, out);
}